// round 3
// baseline (speedup 1.0000x reference)
#include <cuda_runtime.h>
#include <math.h>

// ---------------------------------------------------------------------------
// Problem constants (from reference): B=2, Se=4096, Sd=2048, H=256, NH=4,
// hd=64, F=1024, L=6. All tile dims divide evenly -> no bounds checks needed.
// ---------------------------------------------------------------------------
#define C_B   2
#define C_SE  4096
#define C_SD  2048
#define C_H   256
#define C_NH  4
#define C_F   1024
#define C_L   6

// ---------------------------------------------------------------------------
// Scratch (device globals; no allocations allowed)
// ---------------------------------------------------------------------------
__device__ float g_xenc[C_B * C_SE * C_H];   // encoder input + pos embed
__device__ float g_h   [C_B * C_SD * C_H];   // decoder hidden state
__device__ float g_q   [C_B * C_SD * C_H];
__device__ float g_k   [C_B * C_SE * C_H];   // big enough for cross K
__device__ float g_v   [C_B * C_SE * C_H];
__device__ float g_ctx [C_B * C_SD * C_H];
__device__ float g_tmp [C_B * C_SD * C_H];
__device__ float g_ffn [C_B * C_SD * C_F];

// ---------------------------------------------------------------------------
// Elementwise: x_enc = x + pos_embed (broadcast over batch)
// ---------------------------------------------------------------------------
__global__ void add_pos_kernel(const float* __restrict__ x,
                               const float* __restrict__ pos,
                               float* __restrict__ out, int total, int seh) {
    int i = blockIdx.x * blockDim.x + threadIdx.x;
    if (i < total) out[i] = x[i] + pos[i % seh];
}

// ---------------------------------------------------------------------------
// GELU (tanh approximation -- JAX default approximate=True)
// ---------------------------------------------------------------------------
__device__ __forceinline__ float gelu_f(float x) {
    float x3 = x * x * x;
    return 0.5f * x * (1.0f + tanhf(0.7978845608028654f * (x + 0.044715f * x3)));
}

// ---------------------------------------------------------------------------
// GEMM: C[M,N] = A[M,K] @ W[K,N] + bias[N]  (+ GELU) (+ residual Res[M,N])
// Tiles: 64x64, BK=16, 256 threads, 4x4 register micro-tile.
// A staged transposed in smem (As[k][m]) for conflict-free float4 reads.
// ---------------------------------------------------------------------------
template <bool GELU, bool RES>
__global__ __launch_bounds__(256) void gemm_kernel(
    const float* __restrict__ A, const float* __restrict__ W,
    const float* __restrict__ bias, const float* __restrict__ Res,
    float* __restrict__ C, int M, int N, int K) {
    __shared__ float As[16][64];
    __shared__ float Bs[16][64];

    const int tid = threadIdx.x;
    const int tx = tid & 15, ty = tid >> 4;
    const int m0 = blockIdx.y << 6;
    const int n0 = blockIdx.x << 6;

    const int aRow = tid >> 2;             // 0..63
    const int aCol = (tid & 3) << 2;       // 0,4,8,12
    const int bRow = tid >> 4;             // 0..15
    const int bCol = (tid & 15) << 2;      // 0..60

    const float* Aptr = A + (size_t)(m0 + aRow) * K + aCol;
    const float* Wptr = W + (size_t)bRow * N + n0 + bCol;

    float acc[4][4] = {};

    for (int k0 = 0; k0 < K; k0 += 16) {
        float4 av = *(const float4*)(Aptr + k0);
        As[aCol + 0][aRow] = av.x;
        As[aCol + 1][aRow] = av.y;
        As[aCol + 2][aRow] = av.z;
        As[aCol + 3][aRow] = av.w;
        *(float4*)&Bs[bRow][bCol] = *(const float4*)(Wptr + (size_t)k0 * N);
        __syncthreads();

#pragma unroll
        for (int kk = 0; kk < 16; ++kk) {
            float4 a = *(const float4*)&As[kk][ty << 2];
            float4 b = *(const float4*)&Bs[kk][tx << 2];
            acc[0][0] += a.x * b.x; acc[0][1] += a.x * b.y;
            acc[0][2] += a.x * b.z; acc[0][3] += a.x * b.w;
            acc[1][0] += a.y * b.x; acc[1][1] += a.y * b.y;
            acc[1][2] += a.y * b.z; acc[1][3] += a.y * b.w;
            acc[2][0] += a.z * b.x; acc[2][1] += a.z * b.y;
            acc[2][2] += a.z * b.z; acc[2][3] += a.z * b.w;
            acc[3][0] += a.w * b.x; acc[3][1] += a.w * b.y;
            acc[3][2] += a.w * b.z; acc[3][3] += a.w * b.w;
        }
        __syncthreads();
    }

    float4 bi = *(const float4*)&bias[n0 + (tx << 2)];
#pragma unroll
    for (int i = 0; i < 4; ++i) {
        int row = m0 + (ty << 2) + i;
        float4 v;
        v.x = acc[i][0] + bi.x;
        v.y = acc[i][1] + bi.y;
        v.z = acc[i][2] + bi.z;
        v.w = acc[i][3] + bi.w;
        if (GELU) {
            v.x = gelu_f(v.x); v.y = gelu_f(v.y);
            v.z = gelu_f(v.z); v.w = gelu_f(v.w);
        }
        if (RES) {
            float4 r = *(const float4*)&Res[(size_t)row * N + n0 + (tx << 2)];
            v.x += r.x; v.y += r.y; v.z += r.z; v.w += r.w;
        }
        *(float4*)&C[(size_t)row * N + n0 + (tx << 2)] = v;
    }
}

// ---------------------------------------------------------------------------
// Flash attention (no mask), hd=64, NH=4, H=256.
// One block per (q_tile of 64, b*NH). 64-key tiles. Online softmax with
// 16-lane shuffle reductions (row ty-group spans 16 consecutive lanes).
// K tile smem (KP, stored [d][k]) is reused as the P tile ([q][k]) after the
// score phase so all three 64x64 fp32 buffers fit in exactly 48KB.
// ---------------------------------------------------------------------------
__global__ __launch_bounds__(256) void attn_kernel(
    const float* __restrict__ Q, const float* __restrict__ K,
    const float* __restrict__ V, float* __restrict__ Ctx,
    int Sq, int Sk) {
    const int H = 256;
    __shared__ float QsT[64][64];   // [d][q]
    __shared__ float KP [64][64];   // [d][k] during scores; [q][k] as P after
    __shared__ float Vs [64][64];   // [k][d]

    const int tid = threadIdx.x;
    const int tx = tid & 15, ty = tid >> 4;
    const int q0 = blockIdx.x << 6;
    const int b  = blockIdx.y >> 2;
    const int h0 = (blockIdx.y & 3) << 6;

    // Load Q tile transposed: QsT[d][q]
    {
        int q = tid >> 2;
        int dbase = (tid & 3) << 4;
        const float* qp = Q + ((size_t)(b * Sq + q0 + q)) * H + h0 + dbase;
#pragma unroll
        for (int t = 0; t < 4; ++t) {
            float4 vv = *(const float4*)(qp + 4 * t);
            QsT[dbase + 4 * t + 0][q] = vv.x;
            QsT[dbase + 4 * t + 1][q] = vv.y;
            QsT[dbase + 4 * t + 2][q] = vv.z;
            QsT[dbase + 4 * t + 3][q] = vv.w;
        }
    }

    float m[4], l[4], o[4][4];
#pragma unroll
    for (int i = 0; i < 4; ++i) {
        m[i] = -1e30f; l[i] = 0.0f;
#pragma unroll
        for (int j = 0; j < 4; ++j) o[i][j] = 0.0f;
    }

    for (int k0 = 0; k0 < Sk; k0 += 64) {
        __syncthreads();  // prior consumers of KP/Vs done (also covers QsT on iter 0)
        // Load K tile transposed KP[d][k], V tile natural Vs[k][d]
        {
            int kk = tid >> 2;
            int dbase = (tid & 3) << 4;
            const float* kp = K + ((size_t)(b * Sk + k0 + kk)) * H + h0 + dbase;
#pragma unroll
            for (int t = 0; t < 4; ++t) {
                float4 vv = *(const float4*)(kp + 4 * t);
                KP[dbase + 4 * t + 0][kk] = vv.x;
                KP[dbase + 4 * t + 1][kk] = vv.y;
                KP[dbase + 4 * t + 2][kk] = vv.z;
                KP[dbase + 4 * t + 3][kk] = vv.w;
            }
#pragma unroll
            for (int t = 0; t < 4; ++t) {
                int lin = tid + (t << 8);
                int vk = lin >> 4;
                int d4 = (lin & 15) << 2;
                *(float4*)&Vs[vk][d4] =
                    *(const float4*)(V + ((size_t)(b * Sk + k0 + vk)) * H + h0 + d4);
            }
        }
        __syncthreads();

        // Scores: S[q][k] = sum_d QsT[d][q] * KP[d][k]
        float s[4][4] = {};
#pragma unroll
        for (int d = 0; d < 64; ++d) {
            float4 a  = *(const float4*)&QsT[d][ty << 2];
            float4 bb = *(const float4*)&KP[d][tx << 2];
            s[0][0] += a.x * bb.x; s[0][1] += a.x * bb.y;
            s[0][2] += a.x * bb.z; s[0][3] += a.x * bb.w;
            s[1][0] += a.y * bb.x; s[1][1] += a.y * bb.y;
            s[1][2] += a.y * bb.z; s[1][3] += a.y * bb.w;
            s[2][0] += a.z * bb.x; s[2][1] += a.z * bb.y;
            s[2][2] += a.z * bb.z; s[2][3] += a.z * bb.w;
            s[3][0] += a.w * bb.x; s[3][1] += a.w * bb.y;
            s[3][2] += a.w * bb.z; s[3][3] += a.w * bb.w;
        }
        __syncthreads();  // done reading KP as K; about to overwrite as P

        const float scale = 0.125f;  // 1/sqrt(64)
#pragma unroll
        for (int i = 0; i < 4; ++i) {
            float s0 = s[i][0] * scale, s1 = s[i][1] * scale;
            float s2 = s[i][2] * scale, s3 = s[i][3] * scale;
            float mx = fmaxf(fmaxf(s0, s1), fmaxf(s2, s3));
#pragma unroll
            for (int off = 1; off < 16; off <<= 1)
                mx = fmaxf(mx, __shfl_xor_sync(0xffffffffu, mx, off));
            float mnew = fmaxf(m[i], mx);
            float corr = __expf(m[i] - mnew);
            float p0 = __expf(s0 - mnew);
            float p1 = __expf(s1 - mnew);
            float p2 = __expf(s2 - mnew);
            float p3 = __expf(s3 - mnew);
            float sm = (p0 + p1) + (p2 + p3);
#pragma unroll
            for (int off = 1; off < 16; off <<= 1)
                sm += __shfl_xor_sync(0xffffffffu, sm, off);
            l[i] = l[i] * corr + sm;
            m[i] = mnew;
            o[i][0] *= corr; o[i][1] *= corr; o[i][2] *= corr; o[i][3] *= corr;
            *(float4*)&KP[(ty << 2) + i][tx << 2] = make_float4(p0, p1, p2, p3);
        }
        __syncthreads();  // P visible

        // O += P @ Vtile : o[q][d] += KP[q][kk] * Vs[kk][d]
#pragma unroll
        for (int kk = 0; kk < 64; ++kk) {
            float4 bv = *(const float4*)&Vs[kk][tx << 2];
            float a0 = KP[(ty << 2) + 0][kk];
            float a1 = KP[(ty << 2) + 1][kk];
            float a2 = KP[(ty << 2) + 2][kk];
            float a3 = KP[(ty << 2) + 3][kk];
            o[0][0] += a0 * bv.x; o[0][1] += a0 * bv.y;
            o[0][2] += a0 * bv.z; o[0][3] += a0 * bv.w;
            o[1][0] += a1 * bv.x; o[1][1] += a1 * bv.y;
            o[1][2] += a1 * bv.z; o[1][3] += a1 * bv.w;
            o[2][0] += a2 * bv.x; o[2][1] += a2 * bv.y;
            o[2][2] += a2 * bv.z; o[2][3] += a2 * bv.w;
            o[3][0] += a3 * bv.x; o[3][1] += a3 * bv.y;
            o[3][2] += a3 * bv.z; o[3][3] += a3 * bv.w;
        }
    }

#pragma unroll
    for (int i = 0; i < 4; ++i) {
        float inv = 1.0f / l[i];
        int q = q0 + (ty << 2) + i;
        *(float4*)&Ctx[((size_t)(b * Sq + q)) * H + h0 + (tx << 2)] =
            make_float4(o[i][0] * inv, o[i][1] * inv, o[i][2] * inv, o[i][3] * inv);
    }
}

// ---------------------------------------------------------------------------
// LayerNorm over last dim (H=256). One block (256 threads) per row.
// var is population variance (matches jnp.var), eps = 1e-12.
// ---------------------------------------------------------------------------
__global__ __launch_bounds__(256) void ln_kernel(
    const float* __restrict__ in, const float* __restrict__ gamma,
    const float* __restrict__ beta, float* __restrict__ out) {
    __shared__ float red[256];
    const int row = blockIdx.x, t = threadIdx.x;
    float x = in[(size_t)row * 256 + t];

    red[t] = x;
    __syncthreads();
    for (int s = 128; s > 0; s >>= 1) {
        if (t < s) red[t] += red[t + s];
        __syncthreads();
    }
    float mu = red[0] * (1.0f / 256.0f);
    __syncthreads();

    float d = x - mu;
    red[t] = d * d;
    __syncthreads();
    for (int s = 128; s > 0; s >>= 1) {
        if (t < s) red[t] += red[t + s];
        __syncthreads();
    }
    float var = red[0] * (1.0f / 256.0f);

    out[(size_t)row * 256 + t] = d * rsqrtf(var + 1e-12f) * gamma[t] + beta[t];
}

// ---------------------------------------------------------------------------
// Orchestration
// ---------------------------------------------------------------------------
extern "C" void kernel_launch(void* const* d_in, const int* in_sizes, int n_in,
                              void* d_out, int out_size) {
    const float* x      = (const float*)d_in[0];
    const float* y      = (const float*)d_in[1];
    const float* pos    = (const float*)d_in[2];
    const float* sqkvw  = (const float*)d_in[3];
    const float* sqkvb  = (const float*)d_in[4];
    const float* sow    = (const float*)d_in[5];
    const float* sob    = (const float*)d_in[6];
    const float* cqkvw  = (const float*)d_in[7];
    const float* cqkvb  = (const float*)d_in[8];
    const float* cow    = (const float*)d_in[9];
    const float* cob    = (const float*)d_in[10];
    const float* fw1    = (const float*)d_in[11];
    const float* fb1    = (const float*)d_in[12];
    const float* fw2    = (const float*)d_in[13];
    const float* fb2    = (const float*)d_in[14];
    const float* lng    = (const float*)d_in[15];
    const float* lnb    = (const float*)d_in[16];
    float* out = (float*)d_out;

    const int B = C_B, Se = C_SE, Sd = C_SD, H = C_H, F = C_F, L = C_L, NH = C_NH;
    const int Md = B * Sd;   // 4096 decoder tokens
    const int Me = B * Se;   // 8192 encoder tokens

    float *xenc, *h, *q, *k, *v, *ctx, *tmp, *ffn;
    cudaGetSymbolAddress((void**)&xenc, g_xenc);
    cudaGetSymbolAddress((void**)&h,    g_h);
    cudaGetSymbolAddress((void**)&q,    g_q);
    cudaGetSymbolAddress((void**)&k,    g_k);
    cudaGetSymbolAddress((void**)&v,    g_v);
    cudaGetSymbolAddress((void**)&ctx,  g_ctx);
    cudaGetSymbolAddress((void**)&tmp,  g_tmp);
    cudaGetSymbolAddress((void**)&ffn,  g_ffn);

    // Encoder input + positional embedding
    {
        int total = B * Se * H;
        add_pos_kernel<<<(total + 255) / 256, 256>>>(x, pos, xenc, total, Se * H);
    }
    // h = y
    cudaMemcpyAsync(h, y, sizeof(float) * (size_t)Md * H, cudaMemcpyDeviceToDevice);

    const dim3 gProjH(H / 64, Md / 64);   // [Md,H] outputs
    const dim3 gProjE(H / 64, Me / 64);   // [Me,H] outputs
    const dim3 gFfn1(F / 64, Md / 64);    // [Md,F]
    const dim3 gAttn(Sd / 64, B * NH);

    for (int i = 0; i < L; ++i) {
        const float* sw  = sqkvw + (size_t)i * 3 * H * H;
        const float* sb  = sqkvb + (size_t)i * 3 * H;
        const float* sOw = sow + (size_t)i * H * H;
        const float* sOb = sob + (size_t)i * H;
        const float* cw  = cqkvw + (size_t)i * 3 * H * H;
        const float* cb  = cqkvb + (size_t)i * 3 * H;
        const float* cOw = cow + (size_t)i * H * H;
        const float* cOb = cob + (size_t)i * H;
        const float* w1  = fw1 + (size_t)i * H * F;
        const float* b1  = fb1 + (size_t)i * F;
        const float* w2  = fw2 + (size_t)i * F * H;
        const float* b2  = fb2 + (size_t)i * H;

        // ---- self attention ----
        gemm_kernel<false, false><<<gProjH, 256>>>(h, sw + 0 * H * H, sb + 0 * H, nullptr, q, Md, H, H);
        gemm_kernel<false, false><<<gProjH, 256>>>(h, sw + 1 * H * H, sb + 1 * H, nullptr, k, Md, H, H);
        gemm_kernel<false, false><<<gProjH, 256>>>(h, sw + 2 * H * H, sb + 2 * H, nullptr, v, Md, H, H);
        attn_kernel<<<gAttn, 256>>>(q, k, v, ctx, Sd, Sd);
        gemm_kernel<false, true><<<gProjH, 256>>>(ctx, sOw, sOb, h, tmp, Md, H, H);
        ln_kernel<<<Md, 256>>>(tmp, lng + (size_t)(i * 3 + 0) * H, lnb + (size_t)(i * 3 + 0) * H, h);

        // ---- cross attention ----
        gemm_kernel<false, false><<<gProjH, 256>>>(h,    cw + 0 * H * H, cb + 0 * H, nullptr, q, Md, H, H);
        gemm_kernel<false, false><<<gProjE, 256>>>(xenc, cw + 1 * H * H, cb + 1 * H, nullptr, k, Me, H, H);
        gemm_kernel<false, false><<<gProjE, 256>>>(xenc, cw + 2 * H * H, cb + 2 * H, nullptr, v, Me, H, H);
        attn_kernel<<<gAttn, 256>>>(q, k, v, ctx, Sd, Se);
        gemm_kernel<false, true><<<gProjH, 256>>>(ctx, cOw, cOb, h, tmp, Md, H, H);
        ln_kernel<<<Md, 256>>>(tmp, lng + (size_t)(i * 3 + 1) * H, lnb + (size_t)(i * 3 + 1) * H, h);

        // ---- FFN ----
        gemm_kernel<true, false><<<gFfn1, 256>>>(h, w1, b1, nullptr, ffn, Md, F, H);
        gemm_kernel<false, true><<<gProjH, 256>>>(ffn, w2, b2, h, tmp, Md, H, F);
        ln_kernel<<<Md, 256>>>(tmp, lng + (size_t)(i * 3 + 2) * H, lnb + (size_t)(i * 3 + 2) * H,
                               (i == L - 1) ? out : h);
    }
}

// round 4
// speedup vs baseline: 1.8559x; 1.8559x over previous
#include <cuda_runtime.h>
#include <math.h>
#include <stdint.h>

// ---------------------------------------------------------------------------
// Problem constants: B=2, Se=4096, Sd=2048, H=256, NH=4, hd=64, F=1024, L=6
// ---------------------------------------------------------------------------
#define C_B   2
#define C_SE  4096
#define C_SD  2048
#define C_H   256
#define C_NH  4
#define C_F   1024
#define C_L   6

// ---------------------------------------------------------------------------
// Scratch (device globals; no allocations allowed)
// ---------------------------------------------------------------------------
__device__ float g_xenc[C_B * C_SE * C_H];           // encoder input + pos
__device__ float g_h   [C_B * C_SD * C_H];           // decoder hidden
__device__ float g_qkv [3 * C_B * C_SD * C_H];       // fused self QKV
__device__ float g_q   [C_B * C_SD * C_H];           // cross Q
__device__ float g_kv  [2 * C_B * C_SE * C_H];       // fused cross K,V
__device__ float g_ctx [C_B * C_SD * C_H];
__device__ float g_tmp [C_B * C_SD * C_H];
__device__ float g_ffn [C_B * C_SD * C_F];

// ---------------------------------------------------------------------------
// tf32 helpers + mma wrapper (m16n8k8, row.col, f32 accum)
// ---------------------------------------------------------------------------
__device__ __forceinline__ uint32_t f2tf(float x) {
    uint32_t u;
    asm("cvt.rna.tf32.f32 %0, %1;" : "=r"(u) : "f"(x));
    return u;
}
__device__ __forceinline__ float4 cvt4(float4 v) {
    return make_float4(__uint_as_float(f2tf(v.x)), __uint_as_float(f2tf(v.y)),
                       __uint_as_float(f2tf(v.z)), __uint_as_float(f2tf(v.w)));
}
__device__ __forceinline__ void mma_tf32(float* c, const uint32_t* a,
                                         uint32_t b0, uint32_t b1) {
    asm volatile(
        "mma.sync.aligned.m16n8k8.row.col.f32.tf32.tf32.f32 "
        "{%0,%1,%2,%3}, {%4,%5,%6,%7}, {%8,%9}, {%0,%1,%2,%3};"
        : "+f"(c[0]), "+f"(c[1]), "+f"(c[2]), "+f"(c[3])
        : "r"(a[0]), "r"(a[1]), "r"(a[2]), "r"(a[3]), "r"(b0), "r"(b1));
}

// ---------------------------------------------------------------------------
// Elementwise: x_enc = x + pos_embed (broadcast over batch)
// ---------------------------------------------------------------------------
__global__ void add_pos_kernel(const float* __restrict__ x,
                               const float* __restrict__ pos,
                               float* __restrict__ out, int total, int seh) {
    int i = blockIdx.x * blockDim.x + threadIdx.x;
    if (i < total) out[i] = x[i] + pos[i % seh];
}

__device__ __forceinline__ float gelu_f(float x) {
    float x3 = x * x * x;
    return 0.5f * x * (1.0f + tanhf(0.7978845608028654f * (x + 0.044715f * x3)));
}

// ---------------------------------------------------------------------------
// Tensor-core GEMM: C = A[M,K] @ W + bias (+GELU) (+Res).
// W may be a stack of part matrices, each K x nPart row-major, concatenated:
// output column block n0 uses part = n0/nPart. Output written at
// C + part*M*nPart (so fused QKV lands as [3][M][H] contiguous).
// Tiles: BM=64, BN=64, BK=16; 128 threads = 4 warps (2x2 of 32x32 warp tiles).
// Double-buffered smem; A padded to stride 20, B to stride 72 => all fragment
// LDS are bank-conflict-free. tf32 conversion happens at smem-store time.
// ---------------------------------------------------------------------------
template <bool GELU, bool RES>
__global__ __launch_bounds__(128) void gemm_tc(
    const float* __restrict__ A, const float* __restrict__ W,
    const float* __restrict__ bias, const float* __restrict__ Res,
    float* __restrict__ C, int M, int N, int K, int nPart) {
    __shared__ float As[2][64 * 20];
    __shared__ float Bs[2][16 * 72];

    const int tid = threadIdx.x;
    const int lane = tid & 31, warp = tid >> 5;
    const int g = lane >> 2, c = lane & 3;
    const int wm = warp >> 1, wn = warp & 1;
    const int m0 = blockIdx.y << 6;
    const int n0 = blockIdx.x << 6;
    const int part = n0 / nPart;
    const int nc = n0 - part * nPart;

    const float* Wp = W + (size_t)part * K * nPart + nc;

    const int ar = tid >> 2;            // 0..31
    const int ac = (tid & 3) << 2;      // 0,4,8,12
    const int br = tid >> 4;            // 0..7
    const int bc = (tid & 15) << 2;     // 0..60
    const float* Ap = A + (size_t)(m0 + ar) * K + ac;
    const float* Bp = Wp + (size_t)br * nPart + bc;

    float acc[2][4][4] = {};

    // stage tile 0
    {
        float4 a0 = *(const float4*)(Ap);
        float4 a1 = *(const float4*)(Ap + (size_t)32 * K);
        float4 b0 = *(const float4*)(Bp);
        float4 b1 = *(const float4*)(Bp + (size_t)8 * nPart);
        *(float4*)&As[0][ar * 20 + ac]        = cvt4(a0);
        *(float4*)&As[0][(ar + 32) * 20 + ac] = cvt4(a1);
        *(float4*)&Bs[0][br * 72 + bc]        = cvt4(b0);
        *(float4*)&Bs[0][(br + 8) * 72 + bc]  = cvt4(b1);
    }
    __syncthreads();

    const int KT = K >> 4;
    float4 pa0, pa1, pb0, pb1;
    for (int kt = 0; kt < KT; ++kt) {
        const int buf = kt & 1;
        const bool more = (kt + 1 < KT);
        if (more) {
            int k0 = (kt + 1) << 4;
            pa0 = *(const float4*)(Ap + k0);
            pa1 = *(const float4*)(Ap + (size_t)32 * K + k0);
            pb0 = *(const float4*)(Bp + (size_t)k0 * nPart);
            pb1 = *(const float4*)(Bp + (size_t)(k0 + 8) * nPart);
        }
        const float* Ab = As[buf];
        const float* Bb = Bs[buf];
#pragma unroll
        for (int kk = 0; kk < 16; kk += 8) {
            uint32_t af[2][4];
#pragma unroll
            for (int mf = 0; mf < 2; ++mf) {
                int rb = wm * 32 + mf * 16;
                af[mf][0] = __float_as_uint(Ab[(rb + g) * 20 + kk + c]);
                af[mf][1] = __float_as_uint(Ab[(rb + g + 8) * 20 + kk + c]);
                af[mf][2] = __float_as_uint(Ab[(rb + g) * 20 + kk + c + 4]);
                af[mf][3] = __float_as_uint(Ab[(rb + g + 8) * 20 + kk + c + 4]);
            }
#pragma unroll
            for (int nf = 0; nf < 4; ++nf) {
                int nb = wn * 32 + nf * 8;
                uint32_t b0 = __float_as_uint(Bb[(kk + c) * 72 + nb + g]);
                uint32_t b1 = __float_as_uint(Bb[(kk + c + 4) * 72 + nb + g]);
                mma_tf32(acc[0][nf], af[0], b0, b1);
                mma_tf32(acc[1][nf], af[1], b0, b1);
            }
        }
        if (more) {
            const int nb2 = buf ^ 1;
            *(float4*)&As[nb2][ar * 20 + ac]        = cvt4(pa0);
            *(float4*)&As[nb2][(ar + 32) * 20 + ac] = cvt4(pa1);
            *(float4*)&Bs[nb2][br * 72 + bc]        = cvt4(pb0);
            *(float4*)&Bs[nb2][(br + 8) * 72 + bc]  = cvt4(pb1);
        }
        __syncthreads();
    }

    // epilogue
    const float* bp = bias + (size_t)part * nPart;
    float* Cp = C + (size_t)part * M * nPart;
    const float* Rp = RES ? (Res + (size_t)part * M * nPart) : nullptr;
#pragma unroll
    for (int mf = 0; mf < 2; ++mf) {
        int r0 = m0 + wm * 32 + mf * 16 + g;
#pragma unroll
        for (int nf = 0; nf < 4; ++nf) {
            int col = nc + wn * 32 + nf * 8 + 2 * c;
            float2 bi = *(const float2*)&bp[col];
            float v00 = acc[mf][nf][0] + bi.x;
            float v01 = acc[mf][nf][1] + bi.y;
            float v10 = acc[mf][nf][2] + bi.x;
            float v11 = acc[mf][nf][3] + bi.y;
            if (GELU) {
                v00 = gelu_f(v00); v01 = gelu_f(v01);
                v10 = gelu_f(v10); v11 = gelu_f(v11);
            }
            if (RES) {
                float2 ra = *(const float2*)&Rp[(size_t)r0 * nPart + col];
                float2 rb2 = *(const float2*)&Rp[(size_t)(r0 + 8) * nPart + col];
                v00 += ra.x; v01 += ra.y; v10 += rb2.x; v11 += rb2.y;
            }
            *(float2*)&Cp[(size_t)r0 * nPart + col] = make_float2(v00, v01);
            *(float2*)&Cp[(size_t)(r0 + 8) * nPart + col] = make_float2(v10, v11);
        }
    }
}

// ---------------------------------------------------------------------------
// Tensor-core flash attention: hd=64, NH=4, H=256, no mask.
// Block = 128 threads (4 warps); each warp owns 16 query rows of a 64-q tile.
// Q fragments live in registers (loaded once through smem). K smem is reused
// as the P (probs) buffer after the score phase. All fragment reads are
// conflict-free with stride 68.
// ---------------------------------------------------------------------------
__global__ __launch_bounds__(128) void attn_tc(
    const float* __restrict__ Q, const float* __restrict__ K,
    const float* __restrict__ V, float* __restrict__ Ctx, int Sq, int Sk) {
    const int H = 256;
    __shared__ float Ks[64 * 68];   // K tile [k][d]; later P tile [q][k]
    __shared__ float Vs[64 * 68];   // V tile transposed [d][k]; Q staging first

    const int tid = threadIdx.x;
    const int lane = tid & 31, warp = tid >> 5;
    const int g = lane >> 2, c = lane & 3;
    const int q0 = blockIdx.x << 6;
    const int b  = blockIdx.y >> 2;
    const int h0 = (blockIdx.y & 3) << 6;
    const int sr = tid & 63;             // staging row (0..63)
    const int cb = (tid >> 6) << 5;      // staging col base (0 or 32)
    const int rb = warp << 4;            // this warp's q-row base

    // ---- stage Q through Vs, build register Q fragments ----
    {
        const float* qp = Q + ((size_t)(b * Sq + q0 + sr)) * H + h0 + cb;
#pragma unroll
        for (int t = 0; t < 8; ++t)
            *(float4*)&Vs[sr * 68 + cb + 4 * t] = cvt4(*(const float4*)(qp + 4 * t));
    }
    __syncthreads();
    uint32_t qf[8][4];
#pragma unroll
    for (int dc = 0; dc < 8; ++dc) {
        qf[dc][0] = __float_as_uint(Vs[(rb + g) * 68 + dc * 8 + c]);
        qf[dc][1] = __float_as_uint(Vs[(rb + g + 8) * 68 + dc * 8 + c]);
        qf[dc][2] = __float_as_uint(Vs[(rb + g) * 68 + dc * 8 + c + 4]);
        qf[dc][3] = __float_as_uint(Vs[(rb + g + 8) * 68 + dc * 8 + c + 4]);
    }

    float mr0 = -1e30f, mr1 = -1e30f, l0 = 0.0f, l1 = 0.0f;
    float oacc[8][4] = {};
    const float* Kb = K + (size_t)b * Sk * H + h0;
    const float* Vb = V + (size_t)b * Sk * H + h0;

    for (int k0 = 0; k0 < Sk; k0 += 64) {
        __syncthreads();   // previous tile fully consumed (and Q frags built)
        // ---- stage K [k][d], V transposed [d][k] ----
        {
            const float* kp = Kb + (size_t)(k0 + sr) * H + cb;
#pragma unroll
            for (int t = 0; t < 8; ++t)
                *(float4*)&Ks[sr * 68 + cb + 4 * t] = cvt4(*(const float4*)(kp + 4 * t));
            const float* vp = Vb + (size_t)(k0 + sr) * H + cb;
#pragma unroll
            for (int t = 0; t < 8; ++t) {
                float4 v = *(const float4*)(vp + 4 * t);
                Vs[(cb + 4 * t + 0) * 68 + sr] = __uint_as_float(f2tf(v.x));
                Vs[(cb + 4 * t + 1) * 68 + sr] = __uint_as_float(f2tf(v.y));
                Vs[(cb + 4 * t + 2) * 68 + sr] = __uint_as_float(f2tf(v.z));
                Vs[(cb + 4 * t + 3) * 68 + sr] = __uint_as_float(f2tf(v.w));
            }
        }
        __syncthreads();

        // ---- S = Q @ K^T ----
        float sacc[8][4] = {};
#pragma unroll
        for (int dc = 0; dc < 8; ++dc) {
#pragma unroll
            for (int nt = 0; nt < 8; ++nt) {
                uint32_t b0 = __float_as_uint(Ks[(nt * 8 + g) * 68 + dc * 8 + c]);
                uint32_t b1 = __float_as_uint(Ks[(nt * 8 + g) * 68 + dc * 8 + c + 4]);
                mma_tf32(sacc[nt], qf[dc], b0, b1);
            }
        }
        __syncthreads();   // all warps done reading Ks as K

        // ---- online softmax (rows g and g+8 of warp strip) ----
        const float scale = 0.125f;   // 1/sqrt(64)
        float mx0 = -1e30f, mx1 = -1e30f;
#pragma unroll
        for (int nt = 0; nt < 8; ++nt) {
            sacc[nt][0] *= scale; sacc[nt][1] *= scale;
            sacc[nt][2] *= scale; sacc[nt][3] *= scale;
            mx0 = fmaxf(mx0, fmaxf(sacc[nt][0], sacc[nt][1]));
            mx1 = fmaxf(mx1, fmaxf(sacc[nt][2], sacc[nt][3]));
        }
        mx0 = fmaxf(mx0, __shfl_xor_sync(0xffffffffu, mx0, 1));
        mx0 = fmaxf(mx0, __shfl_xor_sync(0xffffffffu, mx0, 2));
        mx1 = fmaxf(mx1, __shfl_xor_sync(0xffffffffu, mx1, 1));
        mx1 = fmaxf(mx1, __shfl_xor_sync(0xffffffffu, mx1, 2));
        float mn0 = fmaxf(mr0, mx0), mn1 = fmaxf(mr1, mx1);
        float corr0 = __expf(mr0 - mn0), corr1 = __expf(mr1 - mn1);
        float s0 = 0.0f, s1 = 0.0f;
#pragma unroll
        for (int nt = 0; nt < 8; ++nt) {
            float p0 = __expf(sacc[nt][0] - mn0);
            float p1 = __expf(sacc[nt][1] - mn0);
            float p2 = __expf(sacc[nt][2] - mn1);
            float p3 = __expf(sacc[nt][3] - mn1);
            s0 += p0 + p1; s1 += p2 + p3;
            *(float2*)&Ks[(rb + g) * 68 + nt * 8 + 2 * c] =
                make_float2(__uint_as_float(f2tf(p0)), __uint_as_float(f2tf(p1)));
            *(float2*)&Ks[(rb + g + 8) * 68 + nt * 8 + 2 * c] =
                make_float2(__uint_as_float(f2tf(p2)), __uint_as_float(f2tf(p3)));
            oacc[nt][0] *= corr0; oacc[nt][1] *= corr0;
            oacc[nt][2] *= corr1; oacc[nt][3] *= corr1;
        }
        s0 += __shfl_xor_sync(0xffffffffu, s0, 1);
        s0 += __shfl_xor_sync(0xffffffffu, s0, 2);
        s1 += __shfl_xor_sync(0xffffffffu, s1, 1);
        s1 += __shfl_xor_sync(0xffffffffu, s1, 2);
        l0 = l0 * corr0 + s0;
        l1 = l1 * corr1 + s1;
        mr0 = mn0; mr1 = mn1;
        __syncwarp();      // P rows visible within the owning warp

        // ---- O += P @ V ----
#pragma unroll
        for (int kc = 0; kc < 8; ++kc) {
            uint32_t pa[4];
            pa[0] = __float_as_uint(Ks[(rb + g) * 68 + kc * 8 + c]);
            pa[1] = __float_as_uint(Ks[(rb + g + 8) * 68 + kc * 8 + c]);
            pa[2] = __float_as_uint(Ks[(rb + g) * 68 + kc * 8 + c + 4]);
            pa[3] = __float_as_uint(Ks[(rb + g + 8) * 68 + kc * 8 + c + 4]);
#pragma unroll
            for (int nt = 0; nt < 8; ++nt) {
                uint32_t b0 = __float_as_uint(Vs[(nt * 8 + g) * 68 + kc * 8 + c]);
                uint32_t b1 = __float_as_uint(Vs[(nt * 8 + g) * 68 + kc * 8 + c + 4]);
                mma_tf32(oacc[nt], pa, b0, b1);
            }
        }
    }

    // ---- write context ----
    float inv0 = 1.0f / l0, inv1 = 1.0f / l1;
    float* op0 = Ctx + ((size_t)(b * Sq + q0 + rb + g)) * H + h0;
    float* op1 = Ctx + ((size_t)(b * Sq + q0 + rb + g + 8)) * H + h0;
#pragma unroll
    for (int nt = 0; nt < 8; ++nt) {
        *(float2*)&op0[nt * 8 + 2 * c] =
            make_float2(oacc[nt][0] * inv0, oacc[nt][1] * inv0);
        *(float2*)&op1[nt * 8 + 2 * c] =
            make_float2(oacc[nt][2] * inv1, oacc[nt][3] * inv1);
    }
}

// ---------------------------------------------------------------------------
// LayerNorm over last dim (H=256). One block (256 threads) per row.
// ---------------------------------------------------------------------------
__global__ __launch_bounds__(256) void ln_kernel(
    const float* __restrict__ in, const float* __restrict__ gamma,
    const float* __restrict__ beta, float* __restrict__ out) {
    __shared__ float red[256];
    const int row = blockIdx.x, t = threadIdx.x;
    float x = in[(size_t)row * 256 + t];

    red[t] = x;
    __syncthreads();
    for (int s = 128; s > 0; s >>= 1) {
        if (t < s) red[t] += red[t + s];
        __syncthreads();
    }
    float mu = red[0] * (1.0f / 256.0f);
    __syncthreads();

    float d = x - mu;
    red[t] = d * d;
    __syncthreads();
    for (int s = 128; s > 0; s >>= 1) {
        if (t < s) red[t] += red[t + s];
        __syncthreads();
    }
    float var = red[0] * (1.0f / 256.0f);

    out[(size_t)row * 256 + t] = d * rsqrtf(var + 1e-12f) * gamma[t] + beta[t];
}

// ---------------------------------------------------------------------------
// Orchestration
// ---------------------------------------------------------------------------
extern "C" void kernel_launch(void* const* d_in, const int* in_sizes, int n_in,
                              void* d_out, int out_size) {
    const float* x      = (const float*)d_in[0];
    const float* y      = (const float*)d_in[1];
    const float* pos    = (const float*)d_in[2];
    const float* sqkvw  = (const float*)d_in[3];
    const float* sqkvb  = (const float*)d_in[4];
    const float* sow    = (const float*)d_in[5];
    const float* sob    = (const float*)d_in[6];
    const float* cqkvw  = (const float*)d_in[7];
    const float* cqkvb  = (const float*)d_in[8];
    const float* cow    = (const float*)d_in[9];
    const float* cob    = (const float*)d_in[10];
    const float* fw1    = (const float*)d_in[11];
    const float* fb1    = (const float*)d_in[12];
    const float* fw2    = (const float*)d_in[13];
    const float* fb2    = (const float*)d_in[14];
    const float* lng    = (const float*)d_in[15];
    const float* lnb    = (const float*)d_in[16];
    float* out = (float*)d_out;

    const int B = C_B, Se = C_SE, Sd = C_SD, H = C_H, F = C_F, L = C_L, NH = C_NH;
    const int Md = B * Sd;   // 4096
    const int Me = B * Se;   // 8192

    float *xenc, *h, *qkv, *q, *kv, *ctx, *tmp, *ffn;
    cudaGetSymbolAddress((void**)&xenc, g_xenc);
    cudaGetSymbolAddress((void**)&h,    g_h);
    cudaGetSymbolAddress((void**)&qkv,  g_qkv);
    cudaGetSymbolAddress((void**)&q,    g_q);
    cudaGetSymbolAddress((void**)&kv,   g_kv);
    cudaGetSymbolAddress((void**)&ctx,  g_ctx);
    cudaGetSymbolAddress((void**)&tmp,  g_tmp);
    cudaGetSymbolAddress((void**)&ffn,  g_ffn);

    {
        int total = B * Se * H;
        add_pos_kernel<<<(total + 255) / 256, 256>>>(x, pos, xenc, total, Se * H);
    }
    cudaMemcpyAsync(h, y, sizeof(float) * (size_t)Md * H, cudaMemcpyDeviceToDevice);

    const dim3 blk(128);
    const dim3 gSelfQKV(768 / 64, Md / 64);    // 12 x 64
    const dim3 gProj(256 / 64, Md / 64);       // 4 x 64
    const dim3 gCrossKV(512 / 64, Me / 64);    // 8 x 128
    const dim3 gFfn1(1024 / 64, Md / 64);      // 16 x 64
    const dim3 gAttn(Sd / 64, B * NH);         // 32 x 8

    for (int i = 0; i < L; ++i) {
        const float* sw  = sqkvw + (size_t)i * 3 * H * H;
        const float* sb  = sqkvb + (size_t)i * 3 * H;
        const float* sOw = sow + (size_t)i * H * H;
        const float* sOb = sob + (size_t)i * H;
        const float* cw  = cqkvw + (size_t)i * 3 * H * H;
        const float* cb  = cqkvb + (size_t)i * 3 * H;
        const float* cOw = cow + (size_t)i * H * H;
        const float* cOb = cob + (size_t)i * H;
        const float* w1  = fw1 + (size_t)i * H * F;
        const float* b1  = fb1 + (size_t)i * F;
        const float* w2  = fw2 + (size_t)i * F * H;
        const float* b2  = fb2 + (size_t)i * H;

        // ---- self attention ----
        gemm_tc<false, false><<<gSelfQKV, blk>>>(h, sw, sb, nullptr, qkv,
                                                 Md, 768, H, 256);
        attn_tc<<<gAttn, blk>>>(qkv, qkv + (size_t)Md * H, qkv + (size_t)2 * Md * H,
                                ctx, Sd, Sd);
        gemm_tc<false, true><<<gProj, blk>>>(ctx, sOw, sOb, h, tmp, Md, 256, H, 256);
        ln_kernel<<<Md, 256>>>(tmp, lng + (size_t)(i * 3 + 0) * H,
                               lnb + (size_t)(i * 3 + 0) * H, h);

        // ---- cross attention ----
        gemm_tc<false, false><<<gProj, blk>>>(h, cw, cb, nullptr, q, Md, 256, H, 256);
        gemm_tc<false, false><<<gCrossKV, blk>>>(xenc, cw + (size_t)H * H, cb + H,
                                                 nullptr, kv, Me, 512, H, 256);
        attn_tc<<<gAttn, blk>>>(q, kv, kv + (size_t)Me * H, ctx, Sd, Se);
        gemm_tc<false, true><<<gProj, blk>>>(ctx, cOw, cOb, h, tmp, Md, 256, H, 256);
        ln_kernel<<<Md, 256>>>(tmp, lng + (size_t)(i * 3 + 1) * H,
                               lnb + (size_t)(i * 3 + 1) * H, h);

        // ---- FFN ----
        gemm_tc<true, false><<<gFfn1, blk>>>(h, w1, b1, nullptr, ffn, Md, 1024, H, 1024);
        gemm_tc<false, true><<<gProj, blk>>>(ffn, w2, b2, h, tmp, Md, 256, F, 256);
        ln_kernel<<<Md, 256>>>(tmp, lng + (size_t)(i * 3 + 2) * H,
                               lnb + (size_t)(i * 3 + 2) * H,
                               (i == L - 1) ? out : h);
    }
}